// round 3
// baseline (speedup 1.0000x reference)
#include <cuda_runtime.h>
#include <math.h>

#define S_LEN   2048
#define D_MODEL 1024
#define NHEADS  16
#define DKV     64

// Scratch (no allocations allowed) — 32 MB total.
__device__ float g_q[NHEADS * S_LEN * DKV];
__device__ float g_k[NHEADS * S_LEN * DKV];
__device__ float g_v[NHEADS * S_LEN * DKV];
__device__ float g_concat[S_LEN * D_MODEL];

// ---------------------------------------------------------------------------
// Batched GEMM: C[b] = A @ B[b] + bias[b]
// BM=128 rows, BN columns per CTA, BK=16, 256 threads.
// Register blocking: TM=8 rows x TN cols per thread (TN = BN/16).
// A-tile stored transposed in smem (As[k][m]) so the m-fragment is float4s.
// ---------------------------------------------------------------------------
template<int BN, int TN>
__global__ __launch_bounds__(256) void gemm_t(
    const float* __restrict__ A, int lda,
    const float* __restrict__ B, int ldb, long strideB,
    const float* __restrict__ bias, long strideBias,
    float* __restrict__ C, int ldc, long strideC, int K)
{
    constexpr int TM = 8;
    constexpr int BVECS = BN / 64;           // float4s per thread for B tile
    __shared__ float As[16][132];            // [k][m], padded
    __shared__ float Bs[16][BN + 4];         // [k][n], padded

    const int t  = threadIdx.x;
    const int tx = t & 15, ty = t >> 4;
    const int m0 = blockIdx.y * 128, n0 = blockIdx.x * BN;

    const float* Ab    = A + (long)m0 * lda;
    const float* Bb    = B + blockIdx.z * strideB + n0;
    const float* biasb = bias + blockIdx.z * strideBias + n0;
    float*       Cb    = C + blockIdx.z * strideC + (long)m0 * ldc + n0;

    const int ar = t >> 1, ak = (t & 1) << 3;          // A loader: row ar, 8 k's at ak
    const int bk = t >> 4, bn = (t & 15) * (4 * BVECS);// B loader

    float acc[TM][TN] = {};

    for (int k0 = 0; k0 < K; k0 += 16) {
        float4 av[2], bv[BVECS];
#pragma unroll
        for (int v = 0; v < 2; v++)
            av[v] = *(const float4*)&Ab[(long)ar * lda + k0 + ak + 4 * v];
#pragma unroll
        for (int v = 0; v < BVECS; v++)
            bv[v] = *(const float4*)&Bb[(long)(k0 + bk) * ldb + bn + 4 * v];

        __syncthreads();
#pragma unroll
        for (int v = 0; v < 2; v++) {
            As[ak + 4 * v + 0][ar] = av[v].x;
            As[ak + 4 * v + 1][ar] = av[v].y;
            As[ak + 4 * v + 2][ar] = av[v].z;
            As[ak + 4 * v + 3][ar] = av[v].w;
        }
#pragma unroll
        for (int v = 0; v < BVECS; v++)
            *(float4*)&Bs[bk][bn + 4 * v] = bv[v];
        __syncthreads();

#pragma unroll
        for (int kk = 0; kk < 16; kk++) {
            float af[TM], bf[TN];
            *(float4*)&af[0] = *(const float4*)&As[kk][ty * 8];
            *(float4*)&af[4] = *(const float4*)&As[kk][ty * 8 + 4];
#pragma unroll
            for (int v = 0; v < TN / 4; v++)
                *(float4*)&bf[4 * v] = *(const float4*)&Bs[kk][tx * TN + 4 * v];
#pragma unroll
            for (int i = 0; i < TM; i++)
#pragma unroll
                for (int j = 0; j < TN; j++)
                    acc[i][j] += af[i] * bf[j];
        }
    }

    float bb[TN];
#pragma unroll
    for (int j = 0; j < TN; j++) bb[j] = biasb[tx * TN + j];
#pragma unroll
    for (int i = 0; i < TM; i++) {
#pragma unroll
        for (int v = 0; v < TN / 4; v++) {
            float4 o;
            o.x = acc[i][4 * v + 0] + bb[4 * v + 0];
            o.y = acc[i][4 * v + 1] + bb[4 * v + 1];
            o.z = acc[i][4 * v + 2] + bb[4 * v + 2];
            o.w = acc[i][4 * v + 3] + bb[4 * v + 3];
            *(float4*)&Cb[(long)(ty * 8 + i) * ldc + tx * TN + 4 * v] = o;
        }
    }
}

// ---------------------------------------------------------------------------
// Flash attention (fp32, online softmax).
// One CTA per (head, 64-row q tile). 128 threads, 8x4 fragment per thread:
//   tx = t & 15  -> 4 key/dk columns at tx*4
//   ty = t >> 4  -> 8 q-rows at ty*8
// Row groups (16 threads sharing ty) are exact 16-lane shuffle partitions.
// Layouts (stride 68 floats, all float4-aligned):
//   qst [dk][row]   transposed  -> 2 float4 broadcast reads per dk
//   kst [dk][key]   transposed  -> 1 float4 read per dk
//   vs  [key][dk]   row-major   -> 1 float4 read per key
//   ps  [row][key]  row-major   -> float4 stores (<=2-way), scalar bcast reads
// ---------------------------------------------------------------------------
#define AT_STRIDE 68
#define ATT_SMEM_FLOATS (4 * 64 * AT_STRIDE)

__global__ __launch_bounds__(128, 3) void attn_kernel()
{
    extern __shared__ float sm[];
    float* qst = sm;
    float* kst = sm + 64 * AT_STRIDE;
    float* vs  = sm + 2 * 64 * AT_STRIDE;
    float* ps  = sm + 3 * 64 * AT_STRIDE;

    const int t  = threadIdx.x;
    const int tx = t & 15, ty = t >> 4;
    const int h  = blockIdx.y;
    const int m0 = blockIdx.x * 64;

    const float* qh = g_q + ((long)h * S_LEN + m0) * DKV;
    const float* kh = g_k + (long)h * S_LEN * DKV;
    const float* vh = g_v + (long)h * S_LEN * DKV;

    // loader coords: each thread handles half of one 64-float row
    const int lr = t >> 1, lc = (t & 1) << 5;

    // load q tile transposed, pre-scaled by 1/sqrt(DK) = 0.125
#pragma unroll
    for (int j = 0; j < 8; j++) {
        float4 v4 = *(const float4*)&qh[lr * DKV + lc + 4 * j];
        qst[(lc + 4 * j + 0) * AT_STRIDE + lr] = v4.x * 0.125f;
        qst[(lc + 4 * j + 1) * AT_STRIDE + lr] = v4.y * 0.125f;
        qst[(lc + 4 * j + 2) * AT_STRIDE + lr] = v4.z * 0.125f;
        qst[(lc + 4 * j + 3) * AT_STRIDE + lr] = v4.w * 0.125f;
    }

    float m_i[8], l_i[8], acc[8][4];
#pragma unroll
    for (int i = 0; i < 8; i++) {
        m_i[i] = -1e30f; l_i[i] = 0.f;
#pragma unroll
        for (int j = 0; j < 4; j++) acc[i][j] = 0.f;
    }

    for (int kt = 0; kt < S_LEN / 64; kt++) {
        __syncthreads();   // previous iteration done with kst/vs/ps
        {
            const float* kp = kh + (long)(kt * 64 + lr) * DKV + lc;
            const float* vp = vh + (long)(kt * 64 + lr) * DKV + lc;
#pragma unroll
            for (int j = 0; j < 8; j++) {
                float4 k4 = *(const float4*)&kp[4 * j];
                kst[(lc + 4 * j + 0) * AT_STRIDE + lr] = k4.x;
                kst[(lc + 4 * j + 1) * AT_STRIDE + lr] = k4.y;
                kst[(lc + 4 * j + 2) * AT_STRIDE + lr] = k4.z;
                kst[(lc + 4 * j + 3) * AT_STRIDE + lr] = k4.w;
                *(float4*)&vs[lr * AT_STRIDE + lc + 4 * j] = *(const float4*)&vp[4 * j];
            }
        }
        __syncthreads();

        // S = (q*scale) @ K^T : rows ty*8+i, key cols tx*4+j
        float sv[8][4] = {};
#pragma unroll 4
        for (int dk = 0; dk < 64; dk++) {
            float af[8];
            *(float4*)&af[0] = *(const float4*)&qst[dk * AT_STRIDE + ty * 8];
            *(float4*)&af[4] = *(const float4*)&qst[dk * AT_STRIDE + ty * 8 + 4];
            float4 b = *(const float4*)&kst[dk * AT_STRIDE + tx * 4];
#pragma unroll
            for (int i = 0; i < 8; i++) {
                sv[i][0] += af[i] * b.x;
                sv[i][1] += af[i] * b.y;
                sv[i][2] += af[i] * b.z;
                sv[i][3] += af[i] * b.w;
            }
        }

        // online softmax per row (reduce across the 16-lane row group),
        // then stage exp(S) into ps
#pragma unroll
        for (int i = 0; i < 8; i++) {
            float mx = fmaxf(fmaxf(sv[i][0], sv[i][1]), fmaxf(sv[i][2], sv[i][3]));
#pragma unroll
            for (int off = 8; off > 0; off >>= 1)
                mx = fmaxf(mx, __shfl_xor_sync(0xffffffffu, mx, off, 16));
            float mnew = fmaxf(m_i[i], mx);
            float sum = 0.f;
#pragma unroll
            for (int j = 0; j < 4; j++) { sv[i][j] = __expf(sv[i][j] - mnew); sum += sv[i][j]; }
#pragma unroll
            for (int off = 8; off > 0; off >>= 1)
                sum += __shfl_xor_sync(0xffffffffu, sum, off, 16);
            float alpha = __expf(m_i[i] - mnew);
            l_i[i] = l_i[i] * alpha + sum;
            m_i[i] = mnew;
#pragma unroll
            for (int j = 0; j < 4; j++) acc[i][j] *= alpha;
            *(float4*)&ps[(ty * 8 + i) * AT_STRIDE + tx * 4] = *(const float4*)&sv[i][0];
        }
        __syncthreads();

        // acc += P @ V : out cols dk = tx*4..+3
#pragma unroll 4
        for (int key = 0; key < 64; key++) {
            float4 b = *(const float4*)&vs[key * AT_STRIDE + tx * 4];
#pragma unroll
            for (int i = 0; i < 8; i++) {
                float a = ps[(ty * 8 + i) * AT_STRIDE + key];
                acc[i][0] += a * b.x;
                acc[i][1] += a * b.y;
                acc[i][2] += a * b.z;
                acc[i][3] += a * b.w;
            }
        }
    }

    // normalize and write straight into concat layout [s, h*DK + dk]
    float* outp = g_concat + (long)m0 * D_MODEL + h * DKV;
#pragma unroll
    for (int i = 0; i < 8; i++) {
        float inv = 1.f / l_i[i];
        float4 o;
        o.x = acc[i][0] * inv; o.y = acc[i][1] * inv;
        o.z = acc[i][2] * inv; o.w = acc[i][3] * inv;
        *(float4*)&outp[(long)(ty * 8 + i) * D_MODEL + tx * 4] = o;
    }
}

// ---------------------------------------------------------------------------
extern "C" void kernel_launch(void* const* d_in, const int* in_sizes, int n_in,
                              void* d_out, int out_size)
{
    const float* Q  = (const float*)d_in[0];
    const float* K  = (const float*)d_in[1];
    const float* V  = (const float*)d_in[2];
    const float* Wq = (const float*)d_in[3];
    const float* bq = (const float*)d_in[4];
    const float* Wk = (const float*)d_in[5];
    const float* bk = (const float*)d_in[6];
    const float* Wv = (const float*)d_in[7];
    const float* bv = (const float*)d_in[8];
    const float* Wo = (const float*)d_in[9];
    const float* bo = (const float*)d_in[10];
    float* out = (float*)d_out;

    float *pq, *pk, *pv, *pc;
    cudaGetSymbolAddress((void**)&pq, g_q);
    cudaGetSymbolAddress((void**)&pk, g_k);
    cudaGetSymbolAddress((void**)&pv, g_v);
    cudaGetSymbolAddress((void**)&pc, g_concat);

    // Per-head projections: out[h][s][k] = X @ Wx[h] + bx[h]
    dim3 gproj(1, S_LEN / 128, NHEADS);   // 16 x 16 = 256 CTAs
    gemm_t<64, 4><<<gproj, 256>>>(Q, D_MODEL, Wq, DKV, (long)D_MODEL * DKV,
                                  bq, DKV, pq, DKV, (long)S_LEN * DKV, D_MODEL);
    gemm_t<64, 4><<<gproj, 256>>>(K, D_MODEL, Wk, DKV, (long)D_MODEL * DKV,
                                  bk, DKV, pk, DKV, (long)S_LEN * DKV, D_MODEL);
    gemm_t<64, 4><<<gproj, 256>>>(V, D_MODEL, Wv, DKV, (long)D_MODEL * DKV,
                                  bv, DKV, pv, DKV, (long)S_LEN * DKV, D_MODEL);

    // Flash attention -> concat scratch
    cudaFuncSetAttribute(attn_kernel, cudaFuncAttributeMaxDynamicSharedMemorySize,
                         ATT_SMEM_FLOATS * (int)sizeof(float));
    attn_kernel<<<dim3(S_LEN / 64, NHEADS), 128, ATT_SMEM_FLOATS * sizeof(float)>>>();

    // Output projection: out = concat @ Wo + bo
    gemm_t<128, 8><<<dim3(D_MODEL / 128, S_LEN / 128, 1), 256>>>(
        pc, D_MODEL, Wo, D_MODEL, 0, bo, 0, out, D_MODEL, 0, D_MODEL);
}

// round 15
// speedup vs baseline: 1.2543x; 1.2543x over previous
#include <cuda_runtime.h>
#include <cuda_bf16.h>
#include <math.h>

#define S_LEN   2048
#define D_MODEL 1024
#define NHEADS  16
#define DKV     64

// ---------------------------------------------------------------------------
// Scratch (__device__ globals; no allocations allowed)
// ---------------------------------------------------------------------------
__device__ float g_q[NHEADS * S_LEN * DKV];
__device__ float g_k[NHEADS * S_LEN * DKV];
__device__ float g_v[NHEADS * S_LEN * DKV];
__device__ float g_concat[S_LEN * D_MODEL];

// split-bf16 (hi/lo) operands
__device__ __nv_bfloat16 g_qh[S_LEN * D_MODEL], g_ql[S_LEN * D_MODEL];
__device__ __nv_bfloat16 g_kh[S_LEN * D_MODEL], g_kl[S_LEN * D_MODEL];
__device__ __nv_bfloat16 g_vh[S_LEN * D_MODEL], g_vl[S_LEN * D_MODEL];
__device__ __nv_bfloat16 g_ch[S_LEN * D_MODEL], g_cl[S_LEN * D_MODEL];
__device__ __nv_bfloat16 g_wqh[NHEADS * DKV * D_MODEL], g_wql[NHEADS * DKV * D_MODEL];
__device__ __nv_bfloat16 g_wkh[NHEADS * DKV * D_MODEL], g_wkl[NHEADS * DKV * D_MODEL];
__device__ __nv_bfloat16 g_wvh[NHEADS * DKV * D_MODEL], g_wvl[NHEADS * DKV * D_MODEL];
__device__ __nv_bfloat16 g_woh[D_MODEL * D_MODEL], g_wol[D_MODEL * D_MODEL];

// ---------------------------------------------------------------------------
// fp32 -> (hi, lo) bf16 split, same layout
// ---------------------------------------------------------------------------
__global__ __launch_bounds__(256) void split_mat(
    const float* __restrict__ in, __nv_bfloat16* __restrict__ hi,
    __nv_bfloat16* __restrict__ lo, int n)
{
    int i = blockIdx.x * 256 + threadIdx.x;
    if (i < n) {
        float a = in[i];
        __nv_bfloat16 h = __float2bfloat16(a);
        hi[i] = h;
        lo[i] = __float2bfloat16(a - __bfloat162float(h));
    }
}

// W[h][k][n] (fp32) -> hi/lo bf16 transposed to [h][n][k]
__global__ __launch_bounds__(256) void split_w_t(
    const float* __restrict__ in, __nv_bfloat16* __restrict__ hi,
    __nv_bfloat16* __restrict__ lo, int D, int N, int total)
{
    int i = blockIdx.x * 256 + threadIdx.x;
    if (i < total) {
        int per = D * N;
        int h = i / per, r = i % per;
        int n = r / D, k = r % D;
        float a = in[(long)h * per + (long)k * N + n];
        __nv_bfloat16 hh = __float2bfloat16(a);
        hi[i] = hh;
        lo[i] = __float2bfloat16(a - __bfloat162float(hh));
    }
}

// ---------------------------------------------------------------------------
// Tensor-core GEMM with split-bf16 error compensation:
//   C = Ah@Bh + Ah@Bl + Al@Bh + bias       (fp32 accumulate)
// A: [2048][1024] bf16 row-major (hi/lo). B: [batch][N][1024] bf16 (n-major,
// i.e. pre-transposed). Tile: BM=128, BN=64, BK=32. 256 thr = 8 warps (4x2),
// warp tile 32x32 = 2x4 mma(m16n8k16).
// ---------------------------------------------------------------------------
#define SA 40   // smem k-stride (halves): 32 + 8 pad -> conflict-free frags
#define SB 40

#define MMA_BF16(c, a, b) \
    asm volatile("mma.sync.aligned.m16n8k16.row.col.f32.bf16.bf16.f32 " \
                 "{%0,%1,%2,%3},{%4,%5,%6,%7},{%8,%9},{%0,%1,%2,%3};" \
                 : "+f"((c)[0]), "+f"((c)[1]), "+f"((c)[2]), "+f"((c)[3]) \
                 : "r"((a)[0]), "r"((a)[1]), "r"((a)[2]), "r"((a)[3]), \
                   "r"((b)[0]), "r"((b)[1]))

__global__ __launch_bounds__(256) void gemm_mma(
    const __nv_bfloat16* __restrict__ Ah, const __nv_bfloat16* __restrict__ Al,
    const __nv_bfloat16* __restrict__ Bh, const __nv_bfloat16* __restrict__ Bl,
    long strideB,
    const float* __restrict__ bias, long strideBias,
    float* __restrict__ C, int ldc, long strideC)
{
    __shared__ __nv_bfloat16 sAh[128 * SA], sAl[128 * SA];
    __shared__ __nv_bfloat16 sBh[64 * SB],  sBl[64 * SB];

    const int t = threadIdx.x, lane = t & 31, warp = t >> 5;
    const int g = lane >> 2, tid = lane & 3;
    const int wm = (warp & 3) * 32, wn = (warp >> 2) * 32;
    const int m0 = blockIdx.y * 128, n0 = blockIdx.x * 64;

    const __nv_bfloat16* Aph = Ah + (long)m0 * D_MODEL;
    const __nv_bfloat16* Apl = Al + (long)m0 * D_MODEL;
    const __nv_bfloat16* Bph = Bh + blockIdx.z * strideB + (long)n0 * D_MODEL;
    const __nv_bfloat16* Bpl = Bl + blockIdx.z * strideB + (long)n0 * D_MODEL;

    // loader coords: A row t>>1, k-chunk (t&1)*16 (2 x uint4); B row t>>2, k-chunk (t&3)*8
    const int arow = t >> 1, akc = (t & 1) << 4;
    const int brow = t >> 2, bkc = (t & 3) << 3;

    float acc[2][4][4] = {};

    for (int k0 = 0; k0 < D_MODEL; k0 += 32) {
        uint4 ah0 = *(const uint4*)&Aph[(long)arow * D_MODEL + k0 + akc];
        uint4 ah1 = *(const uint4*)&Aph[(long)arow * D_MODEL + k0 + akc + 8];
        uint4 al0 = *(const uint4*)&Apl[(long)arow * D_MODEL + k0 + akc];
        uint4 al1 = *(const uint4*)&Apl[(long)arow * D_MODEL + k0 + akc + 8];
        uint4 bh0 = *(const uint4*)&Bph[(long)brow * D_MODEL + k0 + bkc];
        uint4 bl0 = *(const uint4*)&Bpl[(long)brow * D_MODEL + k0 + bkc];
        __syncthreads();
        *(uint4*)&sAh[arow * SA + akc]     = ah0;
        *(uint4*)&sAh[arow * SA + akc + 8] = ah1;
        *(uint4*)&sAl[arow * SA + akc]     = al0;
        *(uint4*)&sAl[arow * SA + akc + 8] = al1;
        *(uint4*)&sBh[brow * SB + bkc] = bh0;
        *(uint4*)&sBl[brow * SB + bkc] = bl0;
        __syncthreads();

#pragma unroll
        for (int kk = 0; kk < 32; kk += 16) {
            unsigned afh[2][4], afl[2][4], bfh[4][2], bfl[4][2];
#pragma unroll
            for (int mi = 0; mi < 2; mi++) {
                int r0 = wm + mi * 16 + g;
                afh[mi][0] = *(const unsigned*)&sAh[(r0    ) * SA + kk + tid * 2];
                afh[mi][1] = *(const unsigned*)&sAh[(r0 + 8) * SA + kk + tid * 2];
                afh[mi][2] = *(const unsigned*)&sAh[(r0    ) * SA + kk + tid * 2 + 8];
                afh[mi][3] = *(const unsigned*)&sAh[(r0 + 8) * SA + kk + tid * 2 + 8];
                afl[mi][0] = *(const unsigned*)&sAl[(r0    ) * SA + kk + tid * 2];
                afl[mi][1] = *(const unsigned*)&sAl[(r0 + 8) * SA + kk + tid * 2];
                afl[mi][2] = *(const unsigned*)&sAl[(r0    ) * SA + kk + tid * 2 + 8];
                afl[mi][3] = *(const unsigned*)&sAl[(r0 + 8) * SA + kk + tid * 2 + 8];
            }
#pragma unroll
            for (int ni = 0; ni < 4; ni++) {
                int nr = wn + ni * 8 + g;
                bfh[ni][0] = *(const unsigned*)&sBh[nr * SB + kk + tid * 2];
                bfh[ni][1] = *(const unsigned*)&sBh[nr * SB + kk + tid * 2 + 8];
                bfl[ni][0] = *(const unsigned*)&sBl[nr * SB + kk + tid * 2];
                bfl[ni][1] = *(const unsigned*)&sBl[nr * SB + kk + tid * 2 + 8];
            }
#pragma unroll
            for (int mi = 0; mi < 2; mi++)
#pragma unroll
                for (int ni = 0; ni < 4; ni++) {
                    MMA_BF16(acc[mi][ni], afh[mi], bfh[ni]);
                    MMA_BF16(acc[mi][ni], afh[mi], bfl[ni]);
                    MMA_BF16(acc[mi][ni], afl[mi], bfh[ni]);
                }
        }
    }

    const float* bp = bias + blockIdx.z * strideBias;
    float* Cp = C + blockIdx.z * strideC;
#pragma unroll
    for (int mi = 0; mi < 2; mi++)
#pragma unroll
        for (int ni = 0; ni < 4; ni++) {
            int row = m0 + wm + mi * 16 + g;
            int col = n0 + wn + ni * 8 + tid * 2;
            float b0 = bp[col], b1 = bp[col + 1];
            float2 o0 = { acc[mi][ni][0] + b0, acc[mi][ni][1] + b1 };
            float2 o1 = { acc[mi][ni][2] + b0, acc[mi][ni][3] + b1 };
            *(float2*)&Cp[(long)row * ldc + col]       = o0;
            *(float2*)&Cp[(long)(row + 8) * ldc + col] = o1;
        }
}

// ---------------------------------------------------------------------------
// Flash attention (fp32, online softmax).
// One CTA per (head, 64-row q tile). 128 threads, 8x4 fragment per thread.
// ps OVERLAYS kst (smem 52 KB -> 4 CTAs/SM, one full wave of 512 CTAs).
// ---------------------------------------------------------------------------
#define AT_STRIDE 68
#define ATT_SMEM_FLOATS (3 * 64 * AT_STRIDE)

__global__ __launch_bounds__(128, 4) void attn_kernel()
{
    extern __shared__ float sm[];
    float* qst = sm;                         // [dk][row] transposed
    float* kst = sm + 64 * AT_STRIDE;        // [dk][key] transposed  (later: ps)
    float* vs  = sm + 2 * 64 * AT_STRIDE;    // [key][dk]
    float* ps  = kst;                        // [row][key], overlaid

    const int t  = threadIdx.x;
    const int tx = t & 15, ty = t >> 4;
    const int h  = blockIdx.y;
    const int m0 = blockIdx.x * 64;

    const float* qh = g_q + ((long)h * S_LEN + m0) * DKV;
    const float* kh = g_k + (long)h * S_LEN * DKV;
    const float* vh = g_v + (long)h * S_LEN * DKV;

    const int lr = t >> 1, lc = (t & 1) << 5;

    // q tile transposed, pre-scaled by 1/sqrt(DK)
#pragma unroll
    for (int j = 0; j < 8; j++) {
        float4 v4 = *(const float4*)&qh[lr * DKV + lc + 4 * j];
        qst[(lc + 4 * j + 0) * AT_STRIDE + lr] = v4.x * 0.125f;
        qst[(lc + 4 * j + 1) * AT_STRIDE + lr] = v4.y * 0.125f;
        qst[(lc + 4 * j + 2) * AT_STRIDE + lr] = v4.z * 0.125f;
        qst[(lc + 4 * j + 3) * AT_STRIDE + lr] = v4.w * 0.125f;
    }

    float m_i[8], l_i[8], acc[8][4];
#pragma unroll
    for (int i = 0; i < 8; i++) {
        m_i[i] = -1e30f; l_i[i] = 0.f;
#pragma unroll
        for (int j = 0; j < 4; j++) acc[i][j] = 0.f;
    }

    for (int kt = 0; kt < S_LEN / 64; kt++) {
        __syncthreads();   // prior iter done reading ps(=kst)/vs
        {
            const float* kp = kh + (long)(kt * 64 + lr) * DKV + lc;
            const float* vp = vh + (long)(kt * 64 + lr) * DKV + lc;
#pragma unroll
            for (int j = 0; j < 8; j++) {
                float4 k4 = *(const float4*)&kp[4 * j];
                kst[(lc + 4 * j + 0) * AT_STRIDE + lr] = k4.x;
                kst[(lc + 4 * j + 1) * AT_STRIDE + lr] = k4.y;
                kst[(lc + 4 * j + 2) * AT_STRIDE + lr] = k4.z;
                kst[(lc + 4 * j + 3) * AT_STRIDE + lr] = k4.w;
                *(float4*)&vs[lr * AT_STRIDE + lc + 4 * j] = *(const float4*)&vp[4 * j];
            }
        }
        __syncthreads();

        // S = (q*scale) @ K^T
        float sv[8][4] = {};
#pragma unroll 4
        for (int dk = 0; dk < 64; dk++) {
            float af[8];
            *(float4*)&af[0] = *(const float4*)&qst[dk * AT_STRIDE + ty * 8];
            *(float4*)&af[4] = *(const float4*)&qst[dk * AT_STRIDE + ty * 8 + 4];
            float4 b = *(const float4*)&kst[dk * AT_STRIDE + tx * 4];
#pragma unroll
            for (int i = 0; i < 8; i++) {
                sv[i][0] += af[i] * b.x;
                sv[i][1] += af[i] * b.y;
                sv[i][2] += af[i] * b.z;
                sv[i][3] += af[i] * b.w;
            }
        }
        __syncthreads();   // all warps done reading kst before ps overwrite

        // online softmax; stage exp(S) into ps (overlaid on kst)
#pragma unroll
        for (int i = 0; i < 8; i++) {
            float mx = fmaxf(fmaxf(sv[i][0], sv[i][1]), fmaxf(sv[i][2], sv[i][3]));
#pragma unroll
            for (int off = 8; off > 0; off >>= 1)
                mx = fmaxf(mx, __shfl_xor_sync(0xffffffffu, mx, off, 16));
            float mnew = fmaxf(m_i[i], mx);
            float sum = 0.f;
#pragma unroll
            for (int j = 0; j < 4; j++) { sv[i][j] = __expf(sv[i][j] - mnew); sum += sv[i][j]; }
#pragma unroll
            for (int off = 8; off > 0; off >>= 1)
                sum += __shfl_xor_sync(0xffffffffu, sum, off, 16);
            float alpha = __expf(m_i[i] - mnew);
            l_i[i] = l_i[i] * alpha + sum;
            m_i[i] = mnew;
#pragma unroll
            for (int j = 0; j < 4; j++) acc[i][j] *= alpha;
            *(float4*)&ps[(ty * 8 + i) * AT_STRIDE + tx * 4] = *(const float4*)&sv[i][0];
        }
        __syncthreads();

        // acc += P @ V, P read as float4 over keys (12 LDS / 128 FFMA)
#pragma unroll 2
        for (int key0 = 0; key0 < 64; key0 += 4) {
            float p[8][4];
#pragma unroll
            for (int i = 0; i < 8; i++)
                *(float4*)&p[i][0] = *(const float4*)&ps[(ty * 8 + i) * AT_STRIDE + key0];
#pragma unroll
            for (int j = 0; j < 4; j++) {
                float4 b = *(const float4*)&vs[(key0 + j) * AT_STRIDE + tx * 4];
#pragma unroll
                for (int i = 0; i < 8; i++) {
                    acc[i][0] += p[i][j] * b.x;
                    acc[i][1] += p[i][j] * b.y;
                    acc[i][2] += p[i][j] * b.z;
                    acc[i][3] += p[i][j] * b.w;
                }
            }
        }
    }

    float* outp = g_concat + (long)m0 * D_MODEL + h * DKV;
#pragma unroll
    for (int i = 0; i < 8; i++) {
        float inv = 1.f / l_i[i];
        float4 o;
        o.x = acc[i][0] * inv; o.y = acc[i][1] * inv;
        o.z = acc[i][2] * inv; o.w = acc[i][3] * inv;
        *(float4*)&outp[(long)(ty * 8 + i) * D_MODEL + tx * 4] = o;
    }
}

// ---------------------------------------------------------------------------
extern "C" void kernel_launch(void* const* d_in, const int* in_sizes, int n_in,
                              void* d_out, int out_size)
{
    const float* Q  = (const float*)d_in[0];
    const float* K  = (const float*)d_in[1];
    const float* V  = (const float*)d_in[2];
    const float* Wq = (const float*)d_in[3];
    const float* bq = (const float*)d_in[4];
    const float* Wk = (const float*)d_in[5];
    const float* bk = (const float*)d_in[6];
    const float* Wv = (const float*)d_in[7];
    const float* bv = (const float*)d_in[8];
    const float* Wo = (const float*)d_in[9];
    const float* bo = (const float*)d_in[10];
    float* out = (float*)d_out;

    float *pq, *pk, *pv, *pc;
    cudaGetSymbolAddress((void**)&pq, g_q);
    cudaGetSymbolAddress((void**)&pk, g_k);
    cudaGetSymbolAddress((void**)&pv, g_v);
    cudaGetSymbolAddress((void**)&pc, g_concat);
    __nv_bfloat16 *qh, *ql, *kh, *kl, *vh, *vl, *ch, *cl;
    __nv_bfloat16 *wqh, *wql, *wkh, *wkl, *wvh, *wvl, *woh, *wol;
    cudaGetSymbolAddress((void**)&qh, g_qh);   cudaGetSymbolAddress((void**)&ql, g_ql);
    cudaGetSymbolAddress((void**)&kh, g_kh);   cudaGetSymbolAddress((void**)&kl, g_kl);
    cudaGetSymbolAddress((void**)&vh, g_vh);   cudaGetSymbolAddress((void**)&vl, g_vl);
    cudaGetSymbolAddress((void**)&ch, g_ch);   cudaGetSymbolAddress((void**)&cl, g_cl);
    cudaGetSymbolAddress((void**)&wqh, g_wqh); cudaGetSymbolAddress((void**)&wql, g_wql);
    cudaGetSymbolAddress((void**)&wkh, g_wkh); cudaGetSymbolAddress((void**)&wkl, g_wkl);
    cudaGetSymbolAddress((void**)&wvh, g_wvh); cudaGetSymbolAddress((void**)&wvl, g_wvl);
    cudaGetSymbolAddress((void**)&woh, g_woh); cudaGetSymbolAddress((void**)&wol, g_wol);

    const int NMAT = S_LEN * D_MODEL;              // 2M
    const int NW   = NHEADS * D_MODEL * DKV;       // 1M
    const int NWO  = D_MODEL * D_MODEL;            // 1M  (Wo element count)
    const int GB   = (NMAT + 255) / 256, GW = (NW + 255) / 256;

    // split inputs + weights
    split_mat<<<GB, 256>>>(Q, qh, ql, NMAT);
    split_mat<<<GB, 256>>>(K, kh, kl, NMAT);
    split_mat<<<GB, 256>>>(V, vh, vl, NMAT);
    split_w_t<<<GW, 256>>>(Wq, wqh, wql, D_MODEL, DKV, NW);
    split_w_t<<<GW, 256>>>(Wk, wkh, wkl, D_MODEL, DKV, NW);
    split_w_t<<<GW, 256>>>(Wv, wvh, wvl, D_MODEL, DKV, NW);

    // projections: per-head C[h] = X @ W[h] + b[h]   (tensor cores)
    dim3 gproj(1, S_LEN / 128, NHEADS);
    long sB = (long)DKV * D_MODEL, sC = (long)S_LEN * DKV;
    gemm_mma<<<gproj, 256>>>(qh, ql, wqh, wql, sB, bq, DKV, pq, DKV, sC);
    gemm_mma<<<gproj, 256>>>(kh, kl, wkh, wkl, sB, bk, DKV, pk, DKV, sC);
    gemm_mma<<<gproj, 256>>>(vh, vl, wvh, wvl, sB, bv, DKV, pv, DKV, sC);

    // flash attention -> concat
    cudaFuncSetAttribute(attn_kernel, cudaFuncAttributeMaxDynamicSharedMemorySize,
                         ATT_SMEM_FLOATS * (int)sizeof(float));
    attn_kernel<<<dim3(S_LEN / 64, NHEADS), 128, ATT_SMEM_FLOATS * sizeof(float)>>>();

    // out-proj: out = concat @ Wo + bo   (tensor cores)
    split_mat<<<GB, 256>>>(pc, ch, cl, NMAT);
    split_w_t<<<(NWO + 255) / 256, 256>>>(Wo, woh, wol, D_MODEL, D_MODEL, NWO);
    gemm_mma<<<dim3(D_MODEL / 64, S_LEN / 128, 1), 256>>>(
        ch, cl, woh, wol, 0, bo, 0, out, D_MODEL, 0);
}